// round 4
// baseline (speedup 1.0000x reference)
#include <cuda_runtime.h>
#include <math.h>
#include <stdint.h>

// ---------------------------------------------------------------------------
// Problem constants
// ---------------------------------------------------------------------------
namespace {
constexpr int B_  = 2;
constexpr int N_  = 512;
constexpr int D_  = 128;   // DIM
constexpr int PH_ = 64;    // POS_HID
constexpr int AH_ = 512;   // ATTN_HID
constexpr int K_  = 16;    // K_NEIGH
constexpr int M1  = B_ * N_;    // 1024
constexpr int M2  = M1 * K_;    // 16384
}

// ---------------------------------------------------------------------------
// Scratch
// ---------------------------------------------------------------------------
__device__ float g_qkv[M1 * 3 * D_];
__device__ int   g_idx[M1 * K_];
__device__ float g_hid[M2 * PH_];
__device__ float g_PE [M2 * D_];
__device__ float g_H  [M2 * D_];
__device__ float g_VG [M2 * D_];
__device__ float g_A  [M2 * AH_];
__device__ float g_SIM[M2 * D_];

__device__ __forceinline__ uint32_t f2tf32(float f) {
    uint32_t u;
    asm("cvt.rna.tf32.f32 %0, %1;" : "=r"(u) : "f"(f));
    return u;
}

__device__ __forceinline__ void mma_tf32(float c[4],
                                         uint32_t a0, uint32_t a1, uint32_t a2, uint32_t a3,
                                         uint32_t b0, uint32_t b1) {
    asm volatile(
        "mma.sync.aligned.m16n8k8.row.col.f32.tf32.tf32.f32 "
        "{%0,%1,%2,%3}, {%4,%5,%6,%7}, {%8,%9}, {%0,%1,%2,%3};"
        : "+f"(c[0]), "+f"(c[1]), "+f"(c[2]), "+f"(c[3])
        : "r"(a0), "r"(a1), "r"(a2), "r"(a3), "r"(b0), "r"(b1));
}

// ---------------------------------------------------------------------------
// Tensor-core tf32 GEMM with frag-packed double-buffered smem.
//   C[M,N] = [relu]([bias +] A @ W),  W row-major KxN,  N tile = 128.
//   MTW m-tiles(16) per warp; 8 warps as 2x4; BM = MTW*32.
//   TRANSA: A is x (B_,D_,N_), logical A[m][k] = x[b, k, n] (qkv path).
//   Packed smem: A-frag of (mt,ks) for lane L is one uint4; B-frag one uint2.
// ---------------------------------------------------------------------------
template <int MTW, bool RELU, bool TRANSA, bool BIAS>
__global__ __launch_bounds__(256)
void tc_gemm(const float* __restrict__ A, const float* __restrict__ W,
             const float* __restrict__ bias, float* __restrict__ C,
             int M, int N, int K) {
    constexpr int MT = MTW * 2;          // 16-row m-tiles per block
    constexpr int BM = MT * 16;
    __shared__ uint32_t As[2][MT * 512];   // MT*4ks*32lane*4
    __shared__ uint32_t Bs[2][4096];       // 16nt*4ks*32lane*2

    const int tid  = threadIdx.x;
    const int lane = tid & 31;
    const int warp = tid >> 5;
    const int m0 = blockIdx.y * BM;
    const int n0 = blockIdx.x * 128;
    const int wmt = (warp >> 2) * MTW;   // warp's first m-tile
    const int wnt = (warp & 3) * 4;      // warp's first 8-col n-tile

    float acc[MTW][4][4];
#pragma unroll
    for (int mi = 0; mi < MTW; ++mi)
#pragma unroll
        for (int ni = 0; ni < 4; ++ni)
#pragma unroll
            for (int e = 0; e < 4; ++e) acc[mi][ni][e] = 0.f;

    const size_t xb   = TRANSA ? (size_t)(m0 >> 9) * (D_ * N_) : 0;  // batch offset in x
    const int    nlow = TRANSA ? (m0 & (N_ - 1)) : 0;

    auto stage = [&](int t, int buf) {
        const int k0 = t * 32;
        // ---- A tile (BM x 32) ----
#pragma unroll
        for (int u = 0; u < MT / 2; ++u) {
            const int f = tid + u * 256;
            if (!TRANSA) {
                const int r = f >> 3, c0 = (f & 7) << 2;
                const float4 v = *(const float4*)(A + (size_t)(m0 + r) * K + k0 + c0);
                const int mt = r >> 4, ri = r & 15, ks = c0 >> 3;
                const int lb = (ri & 7) << 2;
                const int slot = (((c0 >> 2) & 1) << 1) | (ri >> 3);
                uint32_t* dst = &As[buf][(mt * 4 + ks) * 128];
                dst[((lb + 0) << 2) + slot] = f2tf32(v.x);
                dst[((lb + 1) << 2) + slot] = f2tf32(v.y);
                dst[((lb + 2) << 2) + slot] = f2tf32(v.z);
                dst[((lb + 3) << 2) + slot] = f2tf32(v.w);
            } else {
                const int r0 = (f & 31) << 2, c = f >> 5;   // vec along rows (n of x)
                const float4 v = *(const float4*)(A + xb + (size_t)(k0 + c) * N_ + nlow + r0);
                const int ks = c >> 3;
                const int slotc = ((c >> 2) & 1) << 1;
                float vv[4] = {v.x, v.y, v.z, v.w};
#pragma unroll
                for (int j = 0; j < 4; ++j) {
                    const int r = r0 + j, mt = r >> 4, ri = r & 15;
                    const int lj = ((ri & 7) << 2) | (c & 3);
                    As[buf][(((mt * 4 + ks) * 32 + lj) << 2) + slotc + (ri >> 3)] = f2tf32(vv[j]);
                }
            }
        }
        // ---- B tile (32 x 128) ----
#pragma unroll
        for (int u = 0; u < 4; ++u) {
            const int f = tid + u * 256;
            const int k = f >> 5, nq = (f & 31) << 2;
            const float4 v = *(const float4*)(W + (size_t)(k0 + k) * N + n0 + nq);
            const int ks = k >> 3, slot = (k >> 2) & 1;
            const int nt = nq >> 3, nb = nq & 7;
            uint32_t* dst = &Bs[buf][(nt * 4 + ks) * 64];
            float vv[4] = {v.x, v.y, v.z, v.w};
#pragma unroll
            for (int j = 0; j < 4; ++j)
                dst[((((nb + j) << 2) | (k & 3)) << 1) + slot] = f2tf32(vv[j]);
        }
    };

    auto mmatile = [&](int buf) {
#pragma unroll
        for (int ks = 0; ks < 4; ++ks) {
            uint4 af[MTW];
            uint2 bf[4];
#pragma unroll
            for (int mi = 0; mi < MTW; ++mi)
                af[mi] = *(const uint4*)&As[buf][(((wmt + mi) * 4 + ks) * 32 + lane) << 2];
#pragma unroll
            for (int ni = 0; ni < 4; ++ni)
                bf[ni] = *(const uint2*)&Bs[buf][(((wnt + ni) * 4 + ks) * 32 + lane) << 1];
#pragma unroll
            for (int mi = 0; mi < MTW; ++mi)
#pragma unroll
                for (int ni = 0; ni < 4; ++ni)
                    mma_tf32(acc[mi][ni], af[mi].x, af[mi].y, af[mi].z, af[mi].w,
                             bf[ni].x, bf[ni].y);
        }
    };

    const int T = K >> 5;
    stage(0, 0);
    __syncthreads();
    for (int t = 0; t < T; ++t) {
        if (t + 1 < T) stage(t + 1, (t + 1) & 1);
        mmatile(t & 1);
        __syncthreads();
    }

    // ---- epilogue ----
#pragma unroll
    for (int mi = 0; mi < MTW; ++mi) {
        const int r0 = m0 + (wmt + mi) * 16 + (lane >> 2);
#pragma unroll
        for (int ni = 0; ni < 4; ++ni) {
            const int c0 = n0 + (wnt + ni) * 8 + ((lane & 3) << 1);
            const float bv0 = BIAS ? bias[c0]     : 0.f;
            const float bv1 = BIAS ? bias[c0 + 1] : 0.f;
            float v0 = acc[mi][ni][0] + bv0;
            float v1 = acc[mi][ni][1] + bv1;
            float v2 = acc[mi][ni][2] + bv0;
            float v3 = acc[mi][ni][3] + bv1;
            if (RELU) {
                v0 = fmaxf(v0, 0.f); v1 = fmaxf(v1, 0.f);
                v2 = fmaxf(v2, 0.f); v3 = fmaxf(v3, 0.f);
            }
            *(float2*)(C + (size_t)r0 * N + c0)       = make_float2(v0, v1);
            *(float2*)(C + (size_t)(r0 + 8) * N + c0) = make_float2(v2, v3);
        }
    }
}

// ---------------------------------------------------------------------------
// KNN: 16 smallest distances per query (exact fp32; order-insensitive).
// ---------------------------------------------------------------------------
__global__ void knn_kernel(const float* __restrict__ pos) {
    __shared__ float sx[N_], sy[N_], sz[N_];
    const int lane = threadIdx.x & 31;
    const int warp = threadIdx.x >> 5;
    const int m0 = blockIdx.x * 8;
    const int b = m0 >> 9;

    for (int t = threadIdx.x; t < N_; t += blockDim.x) {
        const float* p = pos + (size_t)(b * N_ + t) * 3;
        sx[t] = p[0]; sy[t] = p[1]; sz[t] = p[2];
    }
    __syncthreads();

    const int m = m0 + warp;
    const int i = m & (N_ - 1);
    const float px = sx[i], py = sy[i], pz = sz[i];

    float d2[16];
#pragma unroll
    for (int t = 0; t < 16; ++t) {
        const int j = lane + 32 * t;
        const float dx = px - sx[j], dy = py - sy[j], dz = pz - sz[j];
        d2[t] = dx * dx + dy * dy + dz * dz;
    }

    unsigned taken = 0u;
    for (int it = 0; it < K_; ++it) {
        float best = 3.4e38f;
        int bt = -1;
#pragma unroll
        for (int t = 0; t < 16; ++t) {
            if (!((taken >> t) & 1u) && d2[t] < best) { best = d2[t]; bt = t; }
        }
        int bj = (bt < 0) ? 0x7fffffff : (lane + 32 * bt);
#pragma unroll
        for (int off = 16; off; off >>= 1) {
            const float ov = __shfl_xor_sync(0xffffffffu, best, off);
            const int   oj = __shfl_xor_sync(0xffffffffu, bj,   off);
            if (ov < best || (ov == best && oj < bj)) { best = ov; bj = oj; }
        }
        if ((bj & 31) == lane) taken |= 1u << (bj >> 5);
        if (lane == 0) g_idx[m * K_ + it] = bj;
    }
}

// ---------------------------------------------------------------------------
// hid = relu(rel_pos @ pw1 + pb1)   (16384 x 64)
// ---------------------------------------------------------------------------
__global__ void hid_kernel(const float* __restrict__ pos,
                           const float* __restrict__ pw1, const float* __restrict__ pb1) {
    const int m = blockIdx.x;
    const int b = m >> 9;
    const int i = m & (N_ - 1);
    const int tid = threadIdx.x;   // 128 = 2 kk x 64 h
    const int h = tid & 63;
    __shared__ float sp[3];
    if (tid < 3) sp[tid] = pos[(size_t)(b * N_ + i) * 3 + tid];
    __syncthreads();
    const float w0 = pw1[h], w1 = pw1[64 + h], w2 = pw1[128 + h], bb = pb1[h];
#pragma unroll
    for (int kp = 0; kp < 8; ++kp) {
        const int kk = kp * 2 + (tid >> 6);
        const int j = g_idx[m * K_ + kk];
        const float* pj = pos + (size_t)(b * N_ + j) * 3;
        const float rx = sp[0] - pj[0], ry = sp[1] - pj[1], rz = sp[2] - pj[2];
        float v = fmaf(rx, w0, fmaf(ry, w1, fmaf(rz, w2, bb)));
        g_hid[(size_t)(m * K_ + kk) * PH_ + h] = fmaxf(v, 0.f);
    }
}

// ---------------------------------------------------------------------------
// build: H = q_i - k_j + pe,  VG = v_j + pe   (coalesced gather)
// ---------------------------------------------------------------------------
__global__ void build_kernel() {
    const int m = blockIdx.x;
    const int b = m >> 9;
    const int tid = threadIdx.x;   // 128
    const float q = g_qkv[(size_t)m * 384 + tid];
#pragma unroll
    for (int kk = 0; kk < K_; ++kk) {
        const int row = m * K_ + kk;
        const int j = g_idx[row];
        const size_t base = (size_t)(b * N_ + j) * 384;
        const float kv = g_qkv[base + 128 + tid];
        const float vv = g_qkv[base + 256 + tid];
        const float pe = g_PE[(size_t)row * D_ + tid];
        g_H [(size_t)row * D_ + tid] = q - kv + pe;
        g_VG[(size_t)row * D_ + tid] = vv + pe;
    }
}

// ---------------------------------------------------------------------------
// finalize: per-channel softmax over k + weighted sum, transposed store.
// ---------------------------------------------------------------------------
__global__ void finalize_kernel(float* __restrict__ out) {
    __shared__ float ss[K_][D_ + 1];
    __shared__ float sv[K_][D_ + 1];
    const int m = blockIdx.x;
    const int b = m >> 9;
    const int i = m & (N_ - 1);
    const int tid = threadIdx.x;   // 128

    for (int t = tid; t < K_ * D_; t += blockDim.x) {
        const int kk = t >> 7, d = t & (D_ - 1);
        ss[kk][d] = g_SIM[(size_t)(m * K_ + kk) * D_ + d];
        sv[kk][d] = g_VG [(size_t)(m * K_ + kk) * D_ + d];
    }
    __syncthreads();

    const int d = tid;
    float mx = -3.4e38f;
#pragma unroll
    for (int kk = 0; kk < K_; ++kk) mx = fmaxf(mx, ss[kk][d]);
    float s = 0.f, agg = 0.f;
#pragma unroll
    for (int kk = 0; kk < K_; ++kk) {
        const float e = expf(ss[kk][d] - mx);
        s += e;
        agg = fmaf(e, sv[kk][d], agg);
    }
    out[(size_t)b * D_ * N_ + (size_t)d * N_ + i] = agg / s;
}

// ---------------------------------------------------------------------------
// Launch
// ---------------------------------------------------------------------------
extern "C" void kernel_launch(void* const* d_in, const int* in_sizes, int n_in,
                              void* d_out, int out_size) {
    const float* x    = (const float*)d_in[0];
    const float* pos  = (const float*)d_in[1];
    const float* wqkv = (const float*)d_in[2];
    const float* pw1  = (const float*)d_in[3];
    const float* pb1  = (const float*)d_in[4];
    const float* pw2  = (const float*)d_in[5];
    const float* pb2  = (const float*)d_in[6];
    const float* aw1  = (const float*)d_in[7];
    const float* ab1  = (const float*)d_in[8];
    const float* aw2  = (const float*)d_in[9];
    const float* ab2  = (const float*)d_in[10];
    float* out = (float*)d_out;

    void *pQKV = nullptr, *pHID = nullptr, *pPE = nullptr,
         *pH = nullptr, *pA = nullptr, *pS = nullptr;
    cudaGetSymbolAddress(&pQKV, g_qkv);
    cudaGetSymbolAddress(&pHID, g_hid);
    cudaGetSymbolAddress(&pPE,  g_PE);
    cudaGetSymbolAddress(&pH,   g_H);
    cudaGetSymbolAddress(&pA,   g_A);
    cudaGetSymbolAddress(&pS,   g_SIM);

    // qkv = x^T @ w_qkv  (tensor core, transposed-A read straight from x)
    tc_gemm<4, false, true, false><<<dim3(3, 8), 256>>>(
        x, wqkv, nullptr, (float*)pQKV, M1, 3 * D_, D_);
    knn_kernel<<<M1 / 8, 256>>>(pos);
    hid_kernel<<<M1, 128>>>(pos, pw1, pb1);
    // pe = hid @ pw2 + pb2
    tc_gemm<4, false, false, true><<<dim3(1, M2 / 128), 256>>>(
        (const float*)pHID, pw2, pb2, (float*)pPE, M2, D_, PH_);
    build_kernel<<<M1, 128>>>();
    // A1 = relu(H @ aw1 + ab1)
    tc_gemm<4, true, false, true><<<dim3(AH_ / 128, M2 / 128), 256>>>(
        (const float*)pH, aw1, ab1, (float*)pA, M2, AH_, D_);
    // SIM = A1 @ aw2 + ab2   (BM=64 -> 256 blocks for better SM coverage)
    tc_gemm<2, false, false, true><<<dim3(1, M2 / 64), 256>>>(
        (const float*)pA, aw2, ab2, (float*)pS, M2, D_, AH_);
    finalize_kernel<<<M1, 128>>>(out);
}

// round 5
// speedup vs baseline: 2.0987x; 2.0987x over previous
#include <cuda_runtime.h>
#include <math.h>
#include <stdint.h>

// ---------------------------------------------------------------------------
// Problem constants
// ---------------------------------------------------------------------------
namespace {
constexpr int B_  = 2;
constexpr int N_  = 512;
constexpr int D_  = 128;   // DIM
constexpr int PH_ = 64;    // POS_HID
constexpr int AH_ = 512;   // ATTN_HID
constexpr int K_  = 16;    // K_NEIGH
constexpr int M1  = B_ * N_;    // 1024
constexpr int M2  = M1 * K_;    // 16384
}

// ---------------------------------------------------------------------------
// Scratch
// ---------------------------------------------------------------------------
__device__ float g_qkv[M1 * 3 * D_];
__device__ int   g_idx[M1 * K_];
__device__ float g_hid[M2 * PH_];
__device__ float g_PE [M2 * D_];
__device__ float g_H  [M2 * D_];
__device__ float g_A  [M2 * AH_];
__device__ float g_SIM[M2 * D_];

// ---------------------------------------------------------------------------
// 1) qkv = x^T @ w_qkv   (one block per (b,n) row)  -- proven R3 version
// ---------------------------------------------------------------------------
__global__ void qkv_kernel(const float* __restrict__ x, const float* __restrict__ w) {
    __shared__ float sx[D_];
    const int m = blockIdx.x;
    const int b = m >> 9;
    const int n = m & (N_ - 1);
    const int tid = threadIdx.x;   // 128 threads
    sx[tid] = x[b * D_ * N_ + tid * N_ + n];
    __syncthreads();
    float a0 = 0.f, a1 = 0.f, a2 = 0.f;
#pragma unroll 8
    for (int d = 0; d < D_; ++d) {
        const float xv = sx[d];
        const float* wr = w + d * (3 * D_);
        a0 = fmaf(xv, wr[tid],           a0);
        a1 = fmaf(xv, wr[tid + D_],      a1);
        a2 = fmaf(xv, wr[tid + 2 * D_],  a2);
    }
    float* o = g_qkv + m * (3 * D_);
    o[tid] = a0; o[tid + D_] = a1; o[tid + 2 * D_] = a2;
}

// ---------------------------------------------------------------------------
// 2) KNN (exact fp32, proven)
// ---------------------------------------------------------------------------
__global__ void knn_kernel(const float* __restrict__ pos) {
    __shared__ float sx[N_], sy[N_], sz[N_];
    const int lane = threadIdx.x & 31;
    const int warp = threadIdx.x >> 5;
    const int m0 = blockIdx.x * 8;
    const int b = m0 >> 9;

    for (int t = threadIdx.x; t < N_; t += blockDim.x) {
        const float* p = pos + (size_t)(b * N_ + t) * 3;
        sx[t] = p[0]; sy[t] = p[1]; sz[t] = p[2];
    }
    __syncthreads();

    const int m = m0 + warp;
    const int i = m & (N_ - 1);
    const float px = sx[i], py = sy[i], pz = sz[i];

    float d2[16];
#pragma unroll
    for (int t = 0; t < 16; ++t) {
        const int j = lane + 32 * t;
        const float dx = px - sx[j], dy = py - sy[j], dz = pz - sz[j];
        d2[t] = dx * dx + dy * dy + dz * dz;
    }

    unsigned taken = 0u;
    for (int it = 0; it < K_; ++it) {
        float best = 3.4e38f;
        int bt = -1;
#pragma unroll
        for (int t = 0; t < 16; ++t) {
            if (!((taken >> t) & 1u) && d2[t] < best) { best = d2[t]; bt = t; }
        }
        int bj = (bt < 0) ? 0x7fffffff : (lane + 32 * bt);
#pragma unroll
        for (int off = 16; off; off >>= 1) {
            const float ov = __shfl_xor_sync(0xffffffffu, best, off);
            const int   oj = __shfl_xor_sync(0xffffffffu, bj,   off);
            if (ov < best || (ov == best && oj < bj)) { best = ov; bj = oj; }
        }
        if ((bj & 31) == lane) taken |= 1u << (bj >> 5);
        if (lane == 0) g_idx[m * K_ + it] = bj;
    }
}

// ---------------------------------------------------------------------------
// 3) hid = relu(rel_pos @ pw1 + pb1)   (16384 x 64)
// ---------------------------------------------------------------------------
__global__ void hid_kernel(const float* __restrict__ pos,
                           const float* __restrict__ pw1, const float* __restrict__ pb1) {
    const int m = blockIdx.x;
    const int b = m >> 9;
    const int i = m & (N_ - 1);
    const int tid = threadIdx.x;   // 128 = 2 kk x 64 h
    const int h = tid & 63;
    __shared__ float sp[3];
    if (tid < 3) sp[tid] = pos[(size_t)(b * N_ + i) * 3 + tid];
    __syncthreads();
    const float w0 = pw1[h], w1 = pw1[64 + h], w2 = pw1[128 + h], bb = pb1[h];
#pragma unroll
    for (int kp = 0; kp < 8; ++kp) {
        const int kk = kp * 2 + (tid >> 6);
        const int j = g_idx[m * K_ + kk];
        const float* pj = pos + (size_t)(b * N_ + j) * 3;
        const float rx = sp[0] - pj[0], ry = sp[1] - pj[1], rz = sp[2] - pj[2];
        float v = fmaf(rx, w0, fmaf(ry, w1, fmaf(rz, w2, bb)));
        g_hid[(size_t)(m * K_ + kk) * PH_ + h] = fmaxf(v, 0.f);
    }
}

// ---------------------------------------------------------------------------
// Tensor-core tf32 GEMM (R3 layout, double-buffered).
//   C = [relu](A @ W + bias). A: MxK row-major, W: KxN row-major.
//   BM=BN=128, BK=32, 8 warps 2x4, warp tile 64x32, mma m16n8k8.
//   FUSEH (pe gemm only): epilogue also writes g_H = q_i - k_j + pe.
// ---------------------------------------------------------------------------
__device__ __forceinline__ uint32_t f2tf32(float f) {
    uint32_t u;
    asm("cvt.rna.tf32.f32 %0, %1;" : "=r"(u) : "f"(f));
    return u;
}

__device__ __forceinline__ void mma_tf32(float c[4],
                                         uint32_t a0, uint32_t a1, uint32_t a2, uint32_t a3,
                                         uint32_t b0, uint32_t b1) {
    asm volatile(
        "mma.sync.aligned.m16n8k8.row.col.f32.tf32.tf32.f32 "
        "{%0,%1,%2,%3}, {%4,%5,%6,%7}, {%8,%9}, {%0,%1,%2,%3};"
        : "+f"(c[0]), "+f"(c[1]), "+f"(c[2]), "+f"(c[3])
        : "r"(a0), "r"(a1), "r"(a2), "r"(a3), "r"(b0), "r"(b1));
}

template <bool RELU, bool FUSEH>
__global__ __launch_bounds__(256)
void tc_gemm(const float* __restrict__ A, const float* __restrict__ W,
             const float* __restrict__ bias, float* __restrict__ C,
             int M, int N, int K) {
    // Padding keeps fragment LDS conflict-free (proven in R3):
    //  A-frag bank = (4r + c) unique over lanes; B-frag bank = (8k + n) unique.
    __shared__ uint32_t As[2][128][36];
    __shared__ uint32_t Bs[2][32][136];

    const int tid  = threadIdx.x;
    const int lane = tid & 31;
    const int warp = tid >> 5;
    const int wm = (warp >> 2) * 64;
    const int wn = (warp & 3) * 32;
    const int m0 = blockIdx.y * 128;
    const int n0 = blockIdx.x * 128;

    float acc[4][4][4];
#pragma unroll
    for (int mi = 0; mi < 4; ++mi)
#pragma unroll
        for (int ni = 0; ni < 4; ++ni)
#pragma unroll
            for (int e = 0; e < 4; ++e) acc[mi][ni][e] = 0.f;

    auto stage = [&](int k0, int buf) {
#pragma unroll
        for (int t = 0; t < 4; ++t) {
            const int idx = tid + t * 256;
            const int r = idx >> 3, c = (idx & 7) << 2;
            const float4 v = *(const float4*)(A + (size_t)(m0 + r) * K + k0 + c);
            As[buf][r][c + 0] = f2tf32(v.x); As[buf][r][c + 1] = f2tf32(v.y);
            As[buf][r][c + 2] = f2tf32(v.z); As[buf][r][c + 3] = f2tf32(v.w);
        }
#pragma unroll
        for (int t = 0; t < 4; ++t) {
            const int idx = tid + t * 256;
            const int kr = idx >> 5, nc = (idx & 31) << 2;
            const float4 v = *(const float4*)(W + (size_t)(k0 + kr) * N + n0 + nc);
            Bs[buf][kr][nc + 0] = f2tf32(v.x); Bs[buf][kr][nc + 1] = f2tf32(v.y);
            Bs[buf][kr][nc + 2] = f2tf32(v.z); Bs[buf][kr][nc + 3] = f2tf32(v.w);
        }
    };

    auto mmatile = [&](int buf) {
#pragma unroll
        for (int ks = 0; ks < 4; ++ks) {
            const int kk = ks * 8;
            uint32_t af[4][4], bf[4][2];
#pragma unroll
            for (int mi = 0; mi < 4; ++mi) {
                const int rb = wm + mi * 16 + (lane >> 2);
                const int cb = kk + (lane & 3);
                af[mi][0] = As[buf][rb    ][cb    ];
                af[mi][1] = As[buf][rb + 8][cb    ];
                af[mi][2] = As[buf][rb    ][cb + 4];
                af[mi][3] = As[buf][rb + 8][cb + 4];
            }
#pragma unroll
            for (int ni = 0; ni < 4; ++ni) {
                const int nb = wn + ni * 8 + (lane >> 2);
                bf[ni][0] = Bs[buf][kk +     (lane & 3)][nb];
                bf[ni][1] = Bs[buf][kk + 4 + (lane & 3)][nb];
            }
#pragma unroll
            for (int mi = 0; mi < 4; ++mi)
#pragma unroll
                for (int ni = 0; ni < 4; ++ni)
                    mma_tf32(acc[mi][ni], af[mi][0], af[mi][1], af[mi][2], af[mi][3],
                             bf[ni][0], bf[ni][1]);
        }
    };

    const int T = K >> 5;
    stage(0, 0);
    __syncthreads();
    for (int t = 0; t < T; ++t) {
        if (t + 1 < T) stage((t + 1) << 5, (t + 1) & 1);
        mmatile(t & 1);
        __syncthreads();
    }

    // ---- epilogue ----
#pragma unroll
    for (int mi = 0; mi < 4; ++mi) {
        const int r0 = m0 + wm + mi * 16 + (lane >> 2);
#pragma unroll
        for (int ni = 0; ni < 4; ++ni) {
            const int c0 = n0 + wn + ni * 8 + ((lane & 3) << 1);
            const float bv0 = bias[c0], bv1 = bias[c0 + 1];
            float v0 = acc[mi][ni][0] + bv0;
            float v1 = acc[mi][ni][1] + bv1;
            float v2 = acc[mi][ni][2] + bv0;
            float v3 = acc[mi][ni][3] + bv1;
            if (RELU) {
                v0 = fmaxf(v0, 0.f); v1 = fmaxf(v1, 0.f);
                v2 = fmaxf(v2, 0.f); v3 = fmaxf(v3, 0.f);
            }
            *(float2*)(C + (size_t)r0 * N + c0)       = make_float2(v0, v1);
            *(float2*)(C + (size_t)(r0 + 8) * N + c0) = make_float2(v2, v3);
            if (FUSEH) {
                // rows of the pe gemm are (m,kk) flat; H = q_i - k_j + pe
#pragma unroll
                for (int rr = 0; rr < 2; ++rr) {
                    const int row = r0 + rr * 8;
                    const int mq  = row >> 4;            // query index (b*512+i)
                    const int bb  = row >> 13;           // batch
                    const int jj  = g_idx[row];
                    const float2 qv = *(const float2*)(g_qkv + (size_t)mq * 384 + c0);
                    const float2 kv = *(const float2*)(g_qkv + (size_t)(bb * N_ + jj) * 384 + 128 + c0);
                    const float p0 = (rr == 0) ? v0 : v2;
                    const float p1 = (rr == 0) ? v1 : v3;
                    *(float2*)(g_H + (size_t)row * D_ + c0) =
                        make_float2(qv.x - kv.x + p0, qv.y - kv.y + p1);
                }
            }
        }
    }
}

// ---------------------------------------------------------------------------
// finalize: per-channel softmax over k + weighted sum (VG built inline).
// ---------------------------------------------------------------------------
__global__ void finalize_kernel(float* __restrict__ out) {
    __shared__ float ss[K_][D_ + 1];
    __shared__ float sv[K_][D_ + 1];
    const int m = blockIdx.x;
    const int b = m >> 9;
    const int i = m & (N_ - 1);
    const int tid = threadIdx.x;   // 128

    for (int t = tid; t < K_ * D_; t += blockDim.x) {
        const int kk = t >> 7, d = t & (D_ - 1);
        const int row = m * K_ + kk;
        const int j = g_idx[row];
        ss[kk][d] = g_SIM[(size_t)row * D_ + d];
        sv[kk][d] = g_qkv[(size_t)(b * N_ + j) * 384 + 256 + d] + g_PE[(size_t)row * D_ + d];
    }
    __syncthreads();

    const int d = tid;
    float mx = -3.4e38f;
#pragma unroll
    for (int kk = 0; kk < K_; ++kk) mx = fmaxf(mx, ss[kk][d]);
    float s = 0.f, agg = 0.f;
#pragma unroll
    for (int kk = 0; kk < K_; ++kk) {
        const float e = expf(ss[kk][d] - mx);
        s += e;
        agg = fmaf(e, sv[kk][d], agg);
    }
    out[(size_t)b * D_ * N_ + (size_t)d * N_ + i] = agg / s;
}

// ---------------------------------------------------------------------------
// Launch
// ---------------------------------------------------------------------------
extern "C" void kernel_launch(void* const* d_in, const int* in_sizes, int n_in,
                              void* d_out, int out_size) {
    const float* x    = (const float*)d_in[0];
    const float* pos  = (const float*)d_in[1];
    const float* wqkv = (const float*)d_in[2];
    const float* pw1  = (const float*)d_in[3];
    const float* pb1  = (const float*)d_in[4];
    const float* pw2  = (const float*)d_in[5];
    const float* pb2  = (const float*)d_in[6];
    const float* aw1  = (const float*)d_in[7];
    const float* ab1  = (const float*)d_in[8];
    const float* aw2  = (const float*)d_in[9];
    const float* ab2  = (const float*)d_in[10];
    float* out = (float*)d_out;

    void *pHID = nullptr, *pPE = nullptr, *pH = nullptr, *pA = nullptr, *pS = nullptr;
    cudaGetSymbolAddress(&pHID, g_hid);
    cudaGetSymbolAddress(&pPE,  g_PE);
    cudaGetSymbolAddress(&pH,   g_H);
    cudaGetSymbolAddress(&pA,   g_A);
    cudaGetSymbolAddress(&pS,   g_SIM);

    qkv_kernel<<<M1, 128>>>(x, wqkv);
    knn_kernel<<<M1 / 8, 256>>>(pos);
    hid_kernel<<<M1, 128>>>(pos, pw1, pb1);
    // pe = hid @ pw2 + pb2; epilogue also builds H = q - k + pe
    tc_gemm<false, true><<<dim3(1, M2 / 128), 256>>>(
        (const float*)pHID, pw2, pb2, (float*)pPE, M2, D_, PH_);
    // A = relu(H @ aw1 + ab1)
    tc_gemm<true, false><<<dim3(AH_ / 128, M2 / 128), 256>>>(
        (const float*)pH, aw1, ab1, (float*)pA, M2, AH_, D_);
    // SIM = A @ aw2 + ab2
    tc_gemm<false, false><<<dim3(1, M2 / 128), 256>>>(
        (const float*)pA, aw2, ab2, (float*)pS, M2, D_, AH_);
    finalize_kernel<<<M1, 128>>>(out);
}